// round 1
// baseline (speedup 1.0000x reference)
#include <cuda_runtime.h>
#include <math.h>

#define B_ 128
#define L_ 512
#define N_ 1023
#define T_ 511
#define D_ 256
#define C_ 511
#define EPS_ 1e-6f

// 128*1023*256 floats = 134 MB scratch (allocs are forbidden -> device global)
__device__ float g_vec[(size_t)B_ * N_ * D_];

// ---------------------------------------------------------------------------
// Zero the node-vector buffer
// ---------------------------------------------------------------------------
__global__ void zero_kernel() {
    size_t total4 = (size_t)B_ * N_ * D_ / 4;
    float4* p = reinterpret_cast<float4*>(g_vec);
    float4 z = make_float4(0.f, 0.f, 0.f, 0.f);
    for (size_t i = (size_t)blockIdx.x * blockDim.x + threadIdx.x; i < total4;
         i += (size_t)gridDim.x * blockDim.x)
        p[i] = z;
}

// ---------------------------------------------------------------------------
// Scatter normalized embedding rows into g_vec. One warp per leaf.
// vec[b, node] = emb[vocab] / (||emb[vocab]|| + eps) if mask else (stays 0)
// ---------------------------------------------------------------------------
__global__ void embed_kernel(const int* __restrict__ leaf_id,   // (B,L,2)
                             const int* __restrict__ mask,      // (B,L)
                             const float* __restrict__ emb) {   // (V,D)
    int leaf = blockIdx.x * 8 + (threadIdx.x >> 5);
    int lane = threadIdx.x & 31;
    if (leaf >= B_ * L_) return;
    if (mask[leaf] == 0) return;
    int b = leaf / L_;
    int node = leaf_id[2 * leaf + 0];
    int vid  = leaf_id[2 * leaf + 1];
    if ((unsigned)node >= (unsigned)N_) return;  // reference drops OOB
    const float4* src = reinterpret_cast<const float4*>(emb + (size_t)vid * D_);
    float4 v0 = src[lane];
    float4 v1 = src[lane + 32];
    float ss = v0.x * v0.x + v0.y * v0.y + v0.z * v0.z + v0.w * v0.w
             + v1.x * v1.x + v1.y * v1.y + v1.z * v1.z + v1.w * v1.w;
#pragma unroll
    for (int o = 16; o > 0; o >>= 1) ss += __shfl_xor_sync(0xffffffffu, ss, o);
    float inv = 1.f / (sqrtf(ss) + EPS_);
    v0.x *= inv; v0.y *= inv; v0.z *= inv; v0.w *= inv;
    v1.x *= inv; v1.y *= inv; v1.z *= inv; v1.w *= inv;
    float4* dst = reinterpret_cast<float4*>(g_vec + ((size_t)b * N_ + node) * D_);
    dst[lane]      = v0;
    dst[lane + 32] = v1;
}

// ---------------------------------------------------------------------------
// Sequential tree composition. One block per batch (batches independent).
// type 0: no-op. type 1: v[p] = v[l].
// type 2: v[p] = normalize( circ_corr(v[l], v[r]) )
//         circ_corr(a,b)[k] = sum_j a[j] * b[(j+k) % D]
// ---------------------------------------------------------------------------
__global__ void __launch_bounds__(256) compose_kernel(const int* __restrict__ comp) {
    __shared__ int   sinfo[T_ * 4];
    __shared__ float sa[D_];
    __shared__ float sb[2 * D_];
    __shared__ float red[8];

    int b = blockIdx.x;
    int tid = threadIdx.x;
    float* v = g_vec + (size_t)b * N_ * D_;

    for (int i = tid; i < T_ * 4; i += 256)
        sinfo[i] = comp[(size_t)b * T_ * 4 + i];
    __syncthreads();

    for (int t = 0; t < T_; ++t) {
        int typ = sinfo[4 * t + 0];
        int p   = sinfo[4 * t + 1];
        int l   = sinfo[4 * t + 2];
        int r   = sinfo[4 * t + 3];
        if (typ == 1) {
            float x = v[(size_t)l * D_ + tid];
            v[(size_t)p * D_ + tid] = x;
            __syncthreads();
        } else if (typ == 2) {
            float av = v[(size_t)l * D_ + tid];
            float bv = v[(size_t)r * D_ + tid];
            sa[tid] = av;
            sb[tid] = bv;
            sb[tid + D_] = bv;
            __syncthreads();
            float acc = 0.f;
#pragma unroll 16
            for (int j = 0; j < D_; ++j)
                acc += sa[j] * sb[j + tid];
            float ss = acc * acc;
#pragma unroll
            for (int o = 16; o > 0; o >>= 1)
                ss += __shfl_xor_sync(0xffffffffu, ss, o);
            if ((tid & 31) == 0) red[tid >> 5] = ss;
            __syncthreads();
            float tot = red[0] + red[1] + red[2] + red[3]
                      + red[4] + red[5] + red[6] + red[7];
            float outv = acc / (sqrtf(tot) + EPS_);
            v[(size_t)p * D_ + tid] = outv;
            __syncthreads();
        }
        // typ == 0: reference writes v[b,0] back to itself -> no-op
    }
}

// ---------------------------------------------------------------------------
// out[m, c] = sum_d g_vec[m, d] * W[c, d] + bias[c]
// M = B*N = 130944 (divisible by 128), K = 256, C = 511.
// BM=128, BN=64, BK=16, 256 threads, 8x4 micro-tile per thread.
// ---------------------------------------------------------------------------
__global__ void __launch_bounds__(256) gemm_kernel(const float* __restrict__ W,
                                                   const float* __restrict__ bias,
                                                   float* __restrict__ out) {
    __shared__ float As[16][132];   // [k][m], padded stride
    __shared__ float Bs[16][68];    // [k][n], padded stride

    const float* A = g_vec;
    int tid = threadIdx.x;
    int m0 = blockIdx.x * 128;
    int n0 = blockIdx.y * 64;
    int tx = tid & 15;        // 0..15 -> 4 output columns each
    int ty = tid >> 4;        // 0..15 -> 8 output rows each
    int lrow = tid >> 2;      // 0..63  loader row
    int lkq  = (tid & 3) * 4; // 0,4,8,12 loader k-quad

    float acc[8][4];
#pragma unroll
    for (int i = 0; i < 8; ++i)
#pragma unroll
        for (int j = 0; j < 4; ++j) acc[i][j] = 0.f;

    int cB = n0 + lrow;
    const float4 z4 = make_float4(0.f, 0.f, 0.f, 0.f);

    for (int k0 = 0; k0 < D_; k0 += 16) {
        // load A tile (128 x 16), transposed into As[k][m]
#pragma unroll
        for (int h = 0; h < 2; ++h) {
            int m = m0 + lrow + 64 * h;
            float4 va = *reinterpret_cast<const float4*>(A + (size_t)m * D_ + k0 + lkq);
            As[lkq + 0][lrow + 64 * h] = va.x;
            As[lkq + 1][lrow + 64 * h] = va.y;
            As[lkq + 2][lrow + 64 * h] = va.z;
            As[lkq + 3][lrow + 64 * h] = va.w;
        }
        // load B tile (64 x 16) from W, transposed into Bs[k][n]
        {
            float4 vb = (cB < C_)
                ? *reinterpret_cast<const float4*>(W + (size_t)cB * D_ + k0 + lkq)
                : z4;
            Bs[lkq + 0][lrow] = vb.x;
            Bs[lkq + 1][lrow] = vb.y;
            Bs[lkq + 2][lrow] = vb.z;
            Bs[lkq + 3][lrow] = vb.w;
        }
        __syncthreads();
#pragma unroll
        for (int k = 0; k < 16; ++k) {
            float4 a0 = *reinterpret_cast<const float4*>(&As[k][ty * 8]);
            float4 a1 = *reinterpret_cast<const float4*>(&As[k][ty * 8 + 4]);
            float4 b0 = *reinterpret_cast<const float4*>(&Bs[k][tx * 4]);
            float a[8] = {a0.x, a0.y, a0.z, a0.w, a1.x, a1.y, a1.z, a1.w};
            float bb[4] = {b0.x, b0.y, b0.z, b0.w};
#pragma unroll
            for (int i = 0; i < 8; ++i)
#pragma unroll
                for (int j = 0; j < 4; ++j)
                    acc[i][j] += a[i] * bb[j];
        }
        __syncthreads();
    }

#pragma unroll
    for (int j = 0; j < 4; ++j) {
        int c = n0 + tx * 4 + j;
        if (c >= C_) continue;
        float bsv = bias[c];
#pragma unroll
        for (int i = 0; i < 8; ++i) {
            int m = m0 + ty * 8 + i;
            out[(size_t)m * C_ + c] = acc[i][j] + bsv;
        }
    }
}

// ---------------------------------------------------------------------------
extern "C" void kernel_launch(void* const* d_in, const int* in_sizes, int n_in,
                              void* d_out, int out_size) {
    // d_in[0] = num_node (unused: always N)
    const int*   leaf_id = (const int*)d_in[1];    // (B,L,2) int32
    const int*   mask    = (const int*)d_in[2];    // (B,L)   int32
    const int*   comp    = (const int*)d_in[3];    // (B,T,4) int32
    const float* emb     = (const float*)d_in[4];  // (V,D)
    const float* W       = (const float*)d_in[5];  // (C,D)
    const float* bias    = (const float*)d_in[6];  // (C,)
    float* out = (float*)d_out;                    // (B,N,C)

    zero_kernel<<<2048, 256>>>();
    embed_kernel<<<(B_ * L_ + 7) / 8, 256>>>(leaf_id, mask, emb);
    compose_kernel<<<B_, 256>>>(comp);
    dim3 grid(1023, 8);   // 130944/128, ceil(511/64)
    gemm_kernel<<<grid, 256>>>(W, bias, out);
}

// round 3
// speedup vs baseline: 1.0709x; 1.0709x over previous
#include <cuda_runtime.h>
#include <math.h>

#define B_ 128
#define L_ 512
#define N_ 1023
#define T_ 511
#define D_ 256
#define C_ 511
#define EPS_ 1e-6f

// 128*1023*256 floats = 134 MB scratch (allocs are forbidden -> device global)
__device__ float g_vec[(size_t)B_ * N_ * D_];

// ---------------------------------------------------------------------------
// Zero the node-vector buffer
// ---------------------------------------------------------------------------
__global__ void zero_kernel() {
    size_t total4 = (size_t)B_ * N_ * D_ / 4;
    float4* p = reinterpret_cast<float4*>(g_vec);
    float4 z = make_float4(0.f, 0.f, 0.f, 0.f);
    for (size_t i = (size_t)blockIdx.x * blockDim.x + threadIdx.x; i < total4;
         i += (size_t)gridDim.x * blockDim.x)
        p[i] = z;
}

// ---------------------------------------------------------------------------
// Scatter normalized embedding rows into g_vec. One warp per leaf.
// ---------------------------------------------------------------------------
__global__ void embed_kernel(const int* __restrict__ leaf_id,   // (B,L,2)
                             const int* __restrict__ mask,      // (B,L)
                             const float* __restrict__ emb) {   // (V,D)
    int leaf = blockIdx.x * 8 + (threadIdx.x >> 5);
    int lane = threadIdx.x & 31;
    if (leaf >= B_ * L_) return;
    if (mask[leaf] == 0) return;
    int b = leaf / L_;
    int node = leaf_id[2 * leaf + 0];
    int vid  = leaf_id[2 * leaf + 1];
    if ((unsigned)node >= (unsigned)N_) return;  // reference drops OOB
    const float4* src = reinterpret_cast<const float4*>(emb + (size_t)vid * D_);
    float4 v0 = src[lane];
    float4 v1 = src[lane + 32];
    float ss = v0.x * v0.x + v0.y * v0.y + v0.z * v0.z + v0.w * v0.w
             + v1.x * v1.x + v1.y * v1.y + v1.z * v1.z + v1.w * v1.w;
#pragma unroll
    for (int o = 16; o > 0; o >>= 1) ss += __shfl_xor_sync(0xffffffffu, ss, o);
    float inv = 1.f / (sqrtf(ss) + EPS_);
    v0.x *= inv; v0.y *= inv; v0.z *= inv; v0.w *= inv;
    v1.x *= inv; v1.y *= inv; v1.z *= inv; v1.w *= inv;
    float4* dst = reinterpret_cast<float4*>(g_vec + ((size_t)b * N_ + node) * D_);
    dst[lane]      = v0;
    dst[lane + 32] = v1;
}

// ---------------------------------------------------------------------------
// Sequential tree composition. One block per batch.
// Register-tiled circular correlation:
//   256 threads = 64 output-groups (t) x 4 j-range groups (g).
//   Thread (t,g) computes partial sums of outputs k = 4t..4t+3 over
//   j in [64g, 64g+64) with a rolling 4-register window of b.
//   b is stored swizzled: phys(i) = i + (i>>2), so that the lane-stride-4
//   logical access becomes lane-stride-5 physical -> conflict-free.
// Note: every g_vec column `tid` is read and written only by thread `tid`,
// so no __syncthreads is needed around the global loads/stores themselves.
// ---------------------------------------------------------------------------
__global__ void __launch_bounds__(256) compose_kernel(const int* __restrict__ comp) {
    __shared__ int sinfo[T_ * 4];
    __shared__ __align__(16) float sa[D_];
    __shared__ float sbw[648];       // swizzled, duplicated b (max phys idx 638)
    __shared__ float pt[4][320];     // partial sums, swizzled column index
    __shared__ float red[8];

    int b = blockIdx.x;
    int tid = threadIdx.x;
    float* v = g_vec + (size_t)b * N_ * D_;

    for (int i = tid; i < T_ * 4; i += 256)
        sinfo[i] = comp[(size_t)b * T_ * 4 + i];
    __syncthreads();

    const int t  = tid & 63;
    const int g  = tid >> 6;
    const int t4 = t * 4;
    const int j0 = g * 64;
    // swizzled read base: logical base idx = j0 + t4 (multiple of 4)
    const int P0 = (j0 + t4) + ((j0 + t4) >> 2);
    const int ftid = tid + (tid >> 2);   // pt column for output k = tid

    for (int ts = 0; ts < T_; ++ts) {
        int typ = sinfo[4 * ts + 0];
        int p   = sinfo[4 * ts + 1];
        int l   = sinfo[4 * ts + 2];
        int r   = sinfo[4 * ts + 3];
        if (typ == 1) {
            // column-private: no sync needed
            v[(size_t)p * D_ + tid] = v[(size_t)l * D_ + tid];
        } else if (typ == 2) {
            float av = v[(size_t)l * D_ + tid];
            float bv = v[(size_t)r * D_ + tid];
            sa[tid] = av;
            int i0 = tid;
            int i1 = tid + 256;
            sbw[i0 + (i0 >> 2)] = bv;
            sbw[i1 + (i1 >> 2)] = bv;
            __syncthreads();

            // init window: w_c = b[j0 + t4 + c]
            float w0 = sbw[P0 + 0];
            float w1 = sbw[P0 + 1];
            float w2 = sbw[P0 + 2];
            float w3 = sbw[P0 + 3];
            float a0 = 0.f, a1 = 0.f, a2 = 0.f, a3 = 0.f;
#pragma unroll
            for (int u = 0; u < 16; ++u) {
                float4 aq = *reinterpret_cast<const float4*>(&sa[j0 + 4 * u]);
                int Pu = P0 + 5 * (u + 1);   // phys(j0+4u+4 + t4)
                a0 += aq.x * w0; a1 += aq.x * w1; a2 += aq.x * w2; a3 += aq.x * w3;
                float n0v = sbw[Pu + 0];
                a0 += aq.y * w1; a1 += aq.y * w2; a2 += aq.y * w3; a3 += aq.y * n0v;
                float n1v = sbw[Pu + 1];
                a0 += aq.z * w2; a1 += aq.z * w3; a2 += aq.z * n0v; a3 += aq.z * n1v;
                float n2v = sbw[Pu + 2];
                a0 += aq.w * w3; a1 += aq.w * n0v; a2 += aq.w * n1v; a3 += aq.w * n2v;
                float n3v = sbw[Pu + 3];
                w0 = n0v; w1 = n1v; w2 = n2v; w3 = n3v;
            }
            // partials: column 5t+c (conflict-free, lane stride 5)
            pt[g][5 * t + 0] = a0;
            pt[g][5 * t + 1] = a1;
            pt[g][5 * t + 2] = a2;
            pt[g][5 * t + 3] = a3;
            __syncthreads();

            float tot = pt[0][ftid] + pt[1][ftid] + pt[2][ftid] + pt[3][ftid];
            float ss = tot * tot;
#pragma unroll
            for (int o = 16; o > 0; o >>= 1)
                ss += __shfl_xor_sync(0xffffffffu, ss, o);
            if ((tid & 31) == 0) red[tid >> 5] = ss;
            __syncthreads();
            float tss = red[0] + red[1] + red[2] + red[3]
                      + red[4] + red[5] + red[6] + red[7];
            v[(size_t)p * D_ + tid] = tot / (sqrtf(tss) + EPS_);
            __syncthreads();   // protects sa/sbw/pt/red reuse next step
        }
        // typ == 0: exact no-op
    }
}

// ---------------------------------------------------------------------------
// out[m, c] = sum_d g_vec[m, d] * W[c, d] + bias[c]
// BM=BN=128, BK=16, 256 threads, 8x8 micro-tile, double-buffered smem,
// smem-staged coalesced epilogue (C=511 odd -> no vector STG to out).
// ---------------------------------------------------------------------------
__global__ void __launch_bounds__(256, 2) gemm_kernel(const float* __restrict__ W,
                                                      const float* __restrict__ bias,
                                                      float* __restrict__ out) {
    __shared__ __align__(16) float As[2][16][132];
    __shared__ __align__(16) float Bs[2][16][132];

    const float* A = g_vec;
    int tid = threadIdx.x;
    int n0 = blockIdx.x * 128;
    int m0 = blockIdx.y * 128;
    int tx = tid & 15;
    int ty = tid >> 4;

    // loaders: 128 rows, each thread owns one 32B half of the 64B row-chunk
    int lrow = tid & 127;
    int lq   = tid >> 7;                    // 0 or 1
    const float* aptr = A + (size_t)(m0 + lrow) * D_ + lq * 8;
    int brow = n0 + lrow;
    bool bvalid = brow < C_;
    const float* bptr = W + (size_t)(bvalid ? brow : 0) * D_ + lq * 8;

    float4 va0, va1, vb0, vb1;
    const float4 z4 = make_float4(0.f, 0.f, 0.f, 0.f);

    // prefetch chunk 0
    va0 = *reinterpret_cast<const float4*>(aptr + 0);
    va1 = *reinterpret_cast<const float4*>(aptr + 4);
    vb0 = bvalid ? *reinterpret_cast<const float4*>(bptr + 0) : z4;
    vb1 = bvalid ? *reinterpret_cast<const float4*>(bptr + 4) : z4;
    {
        int kb = lq * 8;
        As[0][kb + 0][lrow] = va0.x; As[0][kb + 1][lrow] = va0.y;
        As[0][kb + 2][lrow] = va0.z; As[0][kb + 3][lrow] = va0.w;
        As[0][kb + 4][lrow] = va1.x; As[0][kb + 5][lrow] = va1.y;
        As[0][kb + 6][lrow] = va1.z; As[0][kb + 7][lrow] = va1.w;
        Bs[0][kb + 0][lrow] = vb0.x; Bs[0][kb + 1][lrow] = vb0.y;
        Bs[0][kb + 2][lrow] = vb0.z; Bs[0][kb + 3][lrow] = vb0.w;
        Bs[0][kb + 4][lrow] = vb1.x; Bs[0][kb + 5][lrow] = vb1.y;
        Bs[0][kb + 6][lrow] = vb1.z; Bs[0][kb + 7][lrow] = vb1.w;
    }
    __syncthreads();

    float acc[8][8];
#pragma unroll
    for (int i = 0; i < 8; ++i)
#pragma unroll
        for (int j = 0; j < 8; ++j) acc[i][j] = 0.f;

    for (int kt = 0; kt < 16; ++kt) {
        int cur = kt & 1;
        if (kt < 15) {
            const float* ap = aptr + (kt + 1) * 16;
            const float* bp = bptr + (kt + 1) * 16;
            va0 = *reinterpret_cast<const float4*>(ap + 0);
            va1 = *reinterpret_cast<const float4*>(ap + 4);
            vb0 = bvalid ? *reinterpret_cast<const float4*>(bp + 0) : z4;
            vb1 = bvalid ? *reinterpret_cast<const float4*>(bp + 4) : z4;
        }
#pragma unroll
        for (int k = 0; k < 16; ++k) {
            float4 x0 = *reinterpret_cast<const float4*>(&As[cur][k][ty * 8]);
            float4 x1 = *reinterpret_cast<const float4*>(&As[cur][k][ty * 8 + 4]);
            float4 y0 = *reinterpret_cast<const float4*>(&Bs[cur][k][tx * 8]);
            float4 y1 = *reinterpret_cast<const float4*>(&Bs[cur][k][tx * 8 + 4]);
            float a[8] = {x0.x, x0.y, x0.z, x0.w, x1.x, x1.y, x1.z, x1.w};
            float bb[8] = {y0.x, y0.y, y0.z, y0.w, y1.x, y1.y, y1.z, y1.w};
#pragma unroll
            for (int i = 0; i < 8; ++i)
#pragma unroll
                for (int j = 0; j < 8; ++j)
                    acc[i][j] += a[i] * bb[j];
        }
        if (kt < 15) {
            int nxt = cur ^ 1;
            int kb = lq * 8;
            As[nxt][kb + 0][lrow] = va0.x; As[nxt][kb + 1][lrow] = va0.y;
            As[nxt][kb + 2][lrow] = va0.z; As[nxt][kb + 3][lrow] = va0.w;
            As[nxt][kb + 4][lrow] = va1.x; As[nxt][kb + 5][lrow] = va1.y;
            As[nxt][kb + 6][lrow] = va1.z; As[nxt][kb + 7][lrow] = va1.w;
            Bs[nxt][kb + 0][lrow] = vb0.x; Bs[nxt][kb + 1][lrow] = vb0.y;
            Bs[nxt][kb + 2][lrow] = vb0.z; Bs[nxt][kb + 3][lrow] = vb0.w;
            Bs[nxt][kb + 4][lrow] = vb1.x; Bs[nxt][kb + 5][lrow] = vb1.y;
            Bs[nxt][kb + 6][lrow] = vb1.z; Bs[nxt][kb + 7][lrow] = vb1.w;
            __syncthreads();
        }
    }

    // bias per output column
    float bv[8];
#pragma unroll
    for (int j = 0; j < 8; ++j) {
        int c = n0 + tx * 8 + j;
        bv[j] = (c < C_) ? bias[c] : 0.f;
    }

    // Staged epilogue: 4 passes of 32 rows x 128 cols through smem (As reused:
    // 2*16*132 = 4224 floats = 32*132), then fully coalesced scalar STG.
    float* sst = &As[0][0][0];
    __syncthreads();
#pragma unroll
    for (int p = 0; p < 4; ++p) {
        if ((ty >> 2) == p) {
            int r0 = (ty & 3) * 8;
#pragma unroll
            for (int i = 0; i < 8; ++i) {
#pragma unroll
                for (int jq = 0; jq < 2; ++jq) {
                    float4 o;
                    o.x = acc[i][jq * 4 + 0] + bv[jq * 4 + 0];
                    o.y = acc[i][jq * 4 + 1] + bv[jq * 4 + 1];
                    o.z = acc[i][jq * 4 + 2] + bv[jq * 4 + 2];
                    o.w = acc[i][jq * 4 + 3] + bv[jq * 4 + 3];
                    *reinterpret_cast<float4*>(&sst[(r0 + i) * 132 + tx * 8 + jq * 4]) = o;
                }
            }
        }
        __syncthreads();
#pragma unroll
        for (int q = 0; q < 16; ++q) {
            int idx = tid + 256 * q;         // 0..4095
            int row = idx >> 7;
            int col = idx & 127;
            int c = n0 + col;
            if (c < C_)
                out[(size_t)(m0 + p * 32 + row) * C_ + c] = sst[row * 132 + col];
        }
        __syncthreads();
    }
}

// ---------------------------------------------------------------------------
extern "C" void kernel_launch(void* const* d_in, const int* in_sizes, int n_in,
                              void* d_out, int out_size) {
    const int*   leaf_id = (const int*)d_in[1];    // (B,L,2) int32
    const int*   mask    = (const int*)d_in[2];    // (B,L)   int32
    const int*   comp    = (const int*)d_in[3];    // (B,T,4) int32
    const float* emb     = (const float*)d_in[4];  // (V,D)
    const float* W       = (const float*)d_in[5];  // (C,D)
    const float* bias    = (const float*)d_in[6];  // (C,)
    float* out = (float*)d_out;                    // (B,N,C)

    zero_kernel<<<2048, 256>>>();
    embed_kernel<<<(B_ * L_ + 7) / 8, 256>>>(leaf_id, mask, emb);
    compose_kernel<<<B_, 256>>>(comp);
    dim3 grid(4, 1023);   // x = n-tile (fast -> A reuse in L2), y = m-tile
    gemm_kernel<<<grid, 256>>>(W, bias, out);
}

// round 5
// speedup vs baseline: 1.7940x; 1.6753x over previous
#include <cuda_runtime.h>
#include <math.h>
#include <stdint.h>

#define B_ 128
#define L_ 512
#define N_ 1023
#define T_ 511
#define D_ 256
#define C_ 511
#define EPS_ 1e-6f

// 128*1023*256 floats = 134 MB scratch (allocs are forbidden -> device global)
__device__ float g_vec[(size_t)B_ * N_ * D_];

__device__ __forceinline__ uint32_t smem_to_u32(const void* p) {
    uint32_t a;
    asm("{ .reg .u64 t; cvta.to.shared.u64 t, %1; cvt.u32.u64 %0, t; }"
        : "=r"(a) : "l"(p));
    return a;
}

// ---------------------------------------------------------------------------
// Zero the node-vector buffer
// ---------------------------------------------------------------------------
__global__ void zero_kernel() {
    size_t total4 = (size_t)B_ * N_ * D_ / 4;
    float4* p = reinterpret_cast<float4*>(g_vec);
    float4 z = make_float4(0.f, 0.f, 0.f, 0.f);
    for (size_t i = (size_t)blockIdx.x * blockDim.x + threadIdx.x; i < total4;
         i += (size_t)gridDim.x * blockDim.x)
        p[i] = z;
}

// ---------------------------------------------------------------------------
// Scatter normalized embedding rows into g_vec. One warp per leaf.
// ---------------------------------------------------------------------------
__global__ void embed_kernel(const int* __restrict__ leaf_id,
                             const int* __restrict__ mask,
                             const float* __restrict__ emb) {
    int leaf = blockIdx.x * 8 + (threadIdx.x >> 5);
    int lane = threadIdx.x & 31;
    if (leaf >= B_ * L_) return;
    if (mask[leaf] == 0) return;
    int b = leaf / L_;
    int node = leaf_id[2 * leaf + 0];
    int vid  = leaf_id[2 * leaf + 1];
    if ((unsigned)node >= (unsigned)N_) return;
    const float4* src = reinterpret_cast<const float4*>(emb + (size_t)vid * D_);
    float4 v0 = src[lane];
    float4 v1 = src[lane + 32];
    float ss = v0.x * v0.x + v0.y * v0.y + v0.z * v0.z + v0.w * v0.w
             + v1.x * v1.x + v1.y * v1.y + v1.z * v1.z + v1.w * v1.w;
#pragma unroll
    for (int o = 16; o > 0; o >>= 1) ss += __shfl_xor_sync(0xffffffffu, ss, o);
    float inv = 1.f / (sqrtf(ss) + EPS_);
    v0.x *= inv; v0.y *= inv; v0.z *= inv; v0.w *= inv;
    v1.x *= inv; v1.y *= inv; v1.z *= inv; v1.w *= inv;
    float4* dst = reinterpret_cast<float4*>(g_vec + ((size_t)b * N_ + node) * D_);
    dst[lane]      = v0;
    dst[lane + 32] = v1;
}

// ---------------------------------------------------------------------------
// Sequential tree composition (unchanged — known good). One block per batch.
// ---------------------------------------------------------------------------
__global__ void __launch_bounds__(256) compose_kernel(const int* __restrict__ comp) {
    __shared__ int sinfo[T_ * 4];
    __shared__ __align__(16) float sa[D_];
    __shared__ float sbw[648];
    __shared__ float pt[4][320];
    __shared__ float red[8];

    int b = blockIdx.x;
    int tid = threadIdx.x;
    float* v = g_vec + (size_t)b * N_ * D_;

    for (int i = tid; i < T_ * 4; i += 256)
        sinfo[i] = comp[(size_t)b * T_ * 4 + i];
    __syncthreads();

    const int t  = tid & 63;
    const int g  = tid >> 6;
    const int t4 = t * 4;
    const int j0 = g * 64;
    const int P0 = (j0 + t4) + ((j0 + t4) >> 2);
    const int ftid = tid + (tid >> 2);

    for (int ts = 0; ts < T_; ++ts) {
        int typ = sinfo[4 * ts + 0];
        int p   = sinfo[4 * ts + 1];
        int l   = sinfo[4 * ts + 2];
        int r   = sinfo[4 * ts + 3];
        if (typ == 1) {
            v[(size_t)p * D_ + tid] = v[(size_t)l * D_ + tid];
        } else if (typ == 2) {
            float av = v[(size_t)l * D_ + tid];
            float bv = v[(size_t)r * D_ + tid];
            sa[tid] = av;
            int i0 = tid;
            int i1 = tid + 256;
            sbw[i0 + (i0 >> 2)] = bv;
            sbw[i1 + (i1 >> 2)] = bv;
            __syncthreads();

            float w0 = sbw[P0 + 0];
            float w1 = sbw[P0 + 1];
            float w2 = sbw[P0 + 2];
            float w3 = sbw[P0 + 3];
            float a0 = 0.f, a1 = 0.f, a2 = 0.f, a3 = 0.f;
#pragma unroll
            for (int u = 0; u < 16; ++u) {
                float4 aq = *reinterpret_cast<const float4*>(&sa[j0 + 4 * u]);
                int Pu = P0 + 5 * (u + 1);
                a0 += aq.x * w0; a1 += aq.x * w1; a2 += aq.x * w2; a3 += aq.x * w3;
                float n0v = sbw[Pu + 0];
                a0 += aq.y * w1; a1 += aq.y * w2; a2 += aq.y * w3; a3 += aq.y * n0v;
                float n1v = sbw[Pu + 1];
                a0 += aq.z * w2; a1 += aq.z * w3; a2 += aq.z * n0v; a3 += aq.z * n1v;
                float n2v = sbw[Pu + 2];
                a0 += aq.w * w3; a1 += aq.w * n0v; a2 += aq.w * n1v; a3 += aq.w * n2v;
                float n3v = sbw[Pu + 3];
                w0 = n0v; w1 = n1v; w2 = n2v; w3 = n3v;
            }
            pt[g][5 * t + 0] = a0;
            pt[g][5 * t + 1] = a1;
            pt[g][5 * t + 2] = a2;
            pt[g][5 * t + 3] = a3;
            __syncthreads();

            float tot = pt[0][ftid] + pt[1][ftid] + pt[2][ftid] + pt[3][ftid];
            float ss = tot * tot;
#pragma unroll
            for (int o = 16; o > 0; o >>= 1)
                ss += __shfl_xor_sync(0xffffffffu, ss, o);
            if ((tid & 31) == 0) red[tid >> 5] = ss;
            __syncthreads();
            float tss = red[0] + red[1] + red[2] + red[3]
                      + red[4] + red[5] + red[6] + red[7];
            v[(size_t)p * D_ + tid] = tot / (sqrtf(tss) + EPS_);
            __syncthreads();
        }
    }
}

// ---------------------------------------------------------------------------
// tf32 mma.sync GEMM: out[m, c] = sum_d A[m, d] * W[c, d] + bias[c]
// BM=128, BN=128, BK=32, 256 threads (8 warps: 4 along M x 2 along N).
// Warp tile 32x64 = 2 x 8 m16n8k8 tiles. cp.async double-buffered smem,
// stride 36 floats (conflict-free frag LDS.32, 16B-aligned rows).
// ---------------------------------------------------------------------------
#define GS 36          // smem row stride in floats
#define STAGE_F (2 * 128 * GS)   // floats per stage (A tile + B tile)

__device__ __forceinline__ void cp16(uint32_t dst, const void* src) {
    asm volatile("cp.async.ca.shared.global [%0], [%1], 16;"
                 :: "r"(dst), "l"(src) : "memory");
}
__device__ __forceinline__ void cp16z(uint32_t dst, const void* src, int srcsz) {
    asm volatile("cp.async.ca.shared.global [%0], [%1], 16, %2;"
                 :: "r"(dst), "l"(src), "r"(srcsz) : "memory");
}
__device__ __forceinline__ void cp_commit() {
    asm volatile("cp.async.commit_group;" ::: "memory");
}
__device__ __forceinline__ void cp_wait0() {
    asm volatile("cp.async.wait_group 0;" ::: "memory");
}
__device__ __forceinline__ void mma_tf32(float* d, const uint32_t* a,
                                         uint32_t b0, uint32_t b1) {
    asm volatile(
        "mma.sync.aligned.m16n8k8.row.col.f32.tf32.tf32.f32 "
        "{%0,%1,%2,%3}, {%4,%5,%6,%7}, {%8,%9}, {%0,%1,%2,%3};"
        : "+f"(d[0]), "+f"(d[1]), "+f"(d[2]), "+f"(d[3])
        : "r"(a[0]), "r"(a[1]), "r"(a[2]), "r"(a[3]), "r"(b0), "r"(b1));
}

extern __shared__ float gm_smem[];

__global__ void __launch_bounds__(256, 2) gemm_mma_kernel(const float* __restrict__ W,
                                                          const float* __restrict__ bias,
                                                          float* __restrict__ out) {
    const float* A = g_vec;
    int tid = threadIdx.x;
    int wid = tid >> 5;
    int lane = tid & 31;
    int qr = lane >> 2;          // 0..7
    int c4 = lane & 3;           // 0..3
    int wm = wid & 3;            // warp row group (32 rows each)
    int wn = wid >> 2;           // warp col group (64 cols each)

    int n0 = blockIdx.x * 128;
    size_t m0 = (size_t)blockIdx.y * 128;

    // loader role: row = tid>>1 (0..127), half = tid&1 -> k offset half*16
    int lrow = tid >> 1;
    int lhalf = tid & 1;
    const float* asrc = A + (m0 + lrow) * D_ + lhalf * 16;
    int brow = n0 + lrow;
    int bok = (brow < C_) ? 16 : 0;
    const float* bsrc = W + (size_t)(bok ? brow : 0) * D_ + lhalf * 16;

    uint32_t smbase = smem_to_u32(gm_smem);
    uint32_t ldstA = smbase + (uint32_t)(lrow * GS + lhalf * 16) * 4;
    uint32_t ldstB = ldstA + 128 * GS * 4;

    // prefetch stage 0 (k0 = 0)
#pragma unroll
    for (int q = 0; q < 4; ++q) {
        cp16(ldstA + q * 16, asrc + q * 4);
        cp16z(ldstB + q * 16, bsrc + q * 4, bok);
    }
    cp_commit();

    float acc[2][8][4];
#pragma unroll
    for (int mt = 0; mt < 2; ++mt)
#pragma unroll
        for (int nt = 0; nt < 8; ++nt)
#pragma unroll
            for (int u = 0; u < 4; ++u) acc[mt][nt][u] = 0.f;

    cp_wait0();
    __syncthreads();

    for (int bk = 0; bk < 8; ++bk) {
        int cur = bk & 1;
        if (bk < 7) {
            int nxt = cur ^ 1;
            uint32_t dA = ldstA + (uint32_t)(nxt * STAGE_F) * 4;
            uint32_t dB = ldstB + (uint32_t)(nxt * STAGE_F) * 4;
            const float* as = asrc + (bk + 1) * 32;
            const float* bs = bsrc + (bk + 1) * 32;
#pragma unroll
            for (int q = 0; q < 4; ++q) {
                cp16(dA + q * 16, as + q * 4);
                cp16z(dB + q * 16, bs + q * 4, bok);
            }
            cp_commit();
        }

        const float* sA = gm_smem + cur * STAGE_F;
        const float* sB = sA + 128 * GS;
        int ra = wm * 32 + qr;
        int nb = wn * 64 + qr;
#pragma unroll
        for (int s = 0; s < 4; ++s) {
            int kb = 8 * s + c4;
            uint32_t af[2][4];
#pragma unroll
            for (int mt = 0; mt < 2; ++mt) {
                int r0 = ra + mt * 16;
                af[mt][0] = __float_as_uint(sA[r0 * GS + kb]);
                af[mt][1] = __float_as_uint(sA[(r0 + 8) * GS + kb]);
                af[mt][2] = __float_as_uint(sA[r0 * GS + kb + 4]);
                af[mt][3] = __float_as_uint(sA[(r0 + 8) * GS + kb + 4]);
            }
#pragma unroll
            for (int nt = 0; nt < 8; ++nt) {
                int n = nb + nt * 8;
                uint32_t b0 = __float_as_uint(sB[n * GS + kb]);
                uint32_t b1 = __float_as_uint(sB[n * GS + kb + 4]);
                mma_tf32(acc[0][nt], af[0], b0, b1);
                mma_tf32(acc[1][nt], af[1], b0, b1);
            }
        }

        if (bk < 7) cp_wait0();
        __syncthreads();
    }

    // epilogue: direct stores with bias
#pragma unroll
    for (int nt = 0; nt < 8; ++nt) {
        int col = n0 + wn * 64 + nt * 8 + 2 * c4;
        if (col >= C_) continue;
        bool c1ok = (col + 1) < C_;
        float b0v = bias[col];
        float b1v = c1ok ? bias[col + 1] : 0.f;
#pragma unroll
        for (int mt = 0; mt < 2; ++mt) {
            size_t m = m0 + wm * 32 + mt * 16 + qr;
            float* o0 = out + m * C_ + col;
            o0[0] = acc[mt][nt][0] + b0v;
            if (c1ok) o0[1] = acc[mt][nt][1] + b1v;
            float* o1 = out + (m + 8) * C_ + col;
            o1[0] = acc[mt][nt][2] + b0v;
            if (c1ok) o1[1] = acc[mt][nt][3] + b1v;
        }
    }
}

// ---------------------------------------------------------------------------
extern "C" void kernel_launch(void* const* d_in, const int* in_sizes, int n_in,
                              void* d_out, int out_size) {
    const int*   leaf_id = (const int*)d_in[1];    // (B,L,2) int32
    const int*   mask    = (const int*)d_in[2];    // (B,L)   int32
    const int*   comp    = (const int*)d_in[3];    // (B,T,4) int32
    const float* emb     = (const float*)d_in[4];  // (V,D)
    const float* W       = (const float*)d_in[5];  // (C,D)
    const float* bias    = (const float*)d_in[6];  // (C,)
    float* out = (float*)d_out;                    // (B,N,C)

    zero_kernel<<<2048, 256>>>();
    embed_kernel<<<(B_ * L_ + 7) / 8, 256>>>(leaf_id, mask, emb);
    compose_kernel<<<B_, 256>>>(comp);

    static bool attr_set = false;
    if (!attr_set) {
        cudaFuncSetAttribute(gemm_mma_kernel,
                             cudaFuncAttributeMaxDynamicSharedMemorySize,
                             2 * STAGE_F * 4);
        attr_set = true;
    }
    dim3 grid(4, 1023);   // x = n-tile fastest (A tile L2 reuse), y = m-tile
    gemm_mma_kernel<<<grid, 256, 2 * STAGE_F * 4>>>(W, bias, out);
}